// round 9
// baseline (speedup 1.0000x reference)
#include <cuda_runtime.h>
#include <cstdint>

#define COLS   24576
#define KSEL   64
#define NT     512
#define VEC    (COLS / 4 / NT)     // 12 float4 per thread
#define CAP    3840                // candidate capacity (expected ~560 at cut=2.0)
#define SMEM_BYTES ((CAP * 2 + 256) * 4)   // candV + candI + hist = 31.75 KB -> 4 CTAs/SM

// Monotonic float -> uint32 mapping (order-preserving), candidates only.
__device__ __forceinline__ uint32_t f2s(float f) {
    uint32_t b = __float_as_uint(f);
    return (b & 0x80000000u) ? ~b : (b | 0x80000000u);
}
__device__ __forceinline__ float s2f(uint32_t u) {
    uint32_t b = (u & 0x80000000u) ? (u ^ 0x80000000u) : ~u;
    return __uint_as_float(b);
}

__global__ __launch_bounds__(NT, 4)
void topk_relu_scatter(const float* __restrict__ x, float* __restrict__ out) {
    extern __shared__ uint32_t smem[];
    uint32_t* candV = smem;                   // CAP sortable candidate bits
    int*      candI = (int*)(smem + CAP);     // CAP candidate column indices
    uint32_t* hist  = smem + 2 * CAP;         // 256-bin radix histogram
    __shared__ int sCnt, sKth, sEqTot, sNum;
    __shared__ uint32_t sPrefix;

    const int tid = threadIdx.x;
    const long long row = blockIdx.x;

    if (tid == 0) { sCnt = 0; sKth = KSEL; sEqTot = 1; sPrefix = 0u; }
    __syncthreads();

    const float4* __restrict__ rowv = (const float4*)(x + row * (long long)COLS);
    float4* __restrict__ outv = (float4*)(out + row * (long long)COLS);

    // ---- Phase 1: stream row (L2-resident, skip L1); vector max filter;
    //               rare-path push of (value, index). ----
    float cutf = 2.0f;
#pragma unroll 4
    for (int j = 0; j < VEC; j++) {
        const int i = j * NT + tid;
        float4 f = __ldcg(rowv + i);
        float m = fmaxf(fmaxf(f.x, f.y), fmaxf(f.z, f.w));
        if (m > cutf) {                       // ~8.8% of vectors
            if (f.x > cutf) { int p = atomicAdd(&sCnt, 1); if (p < CAP) { candV[p] = f2s(f.x); candI[p] = 4*i+0; } }
            if (f.y > cutf) { int p = atomicAdd(&sCnt, 1); if (p < CAP) { candV[p] = f2s(f.y); candI[p] = 4*i+1; } }
            if (f.z > cutf) { int p = atomicAdd(&sCnt, 1); if (p < CAP) { candV[p] = f2s(f.z); candI[p] = 4*i+2; } }
            if (f.w > cutf) { int p = atomicAdd(&sCnt, 1); if (p < CAP) { candV[p] = f2s(f.w); candI[p] = 4*i+3; } }
        }
    }
    __syncthreads();
    int cnt = sCnt;

    // ---- Robustness fallback (never taken for N(0,1); re-read = L2 hits) ----
    if (cnt > CAP || cnt < KSEL) {
        cutf = (cnt < KSEL) ? 0.0f : 3.0f;    // ReLU makes cut=0.0 fully general
        __syncthreads();
        if (tid == 0) sCnt = 0;
        __syncthreads();
        for (int j = 0; j < VEC; j++) {
            const int i = j * NT + tid;
            float4 f = __ldcg(rowv + i);
            float m = fmaxf(fmaxf(f.x, f.y), fmaxf(f.z, f.w));
            if (m > cutf) {
                if (f.x > cutf) { int p = atomicAdd(&sCnt, 1); if (p < CAP) { candV[p] = f2s(f.x); candI[p] = 4*i+0; } }
                if (f.y > cutf) { int p = atomicAdd(&sCnt, 1); if (p < CAP) { candV[p] = f2s(f.y); candI[p] = 4*i+1; } }
                if (f.z > cutf) { int p = atomicAdd(&sCnt, 1); if (p < CAP) { candV[p] = f2s(f.z); candI[p] = 4*i+2; } }
                if (f.w > cutf) { int p = atomicAdd(&sCnt, 1); if (p < CAP) { candV[p] = f2s(f.w); candI[p] = 4*i+3; } }
            }
        }
        __syncthreads();
        cnt = min(sCnt, CAP);
    }

    // ---- Phase 2: exact K-th largest among candidates (4x8-bit radix select) ----
    float Tf = 0.0f;
    uint32_t T = 0u;
    int eqAllow = 0, eqTotal = 0;
    bool degenerate = (cnt <= KSEL);          // all candidates win
    if (!degenerate) {
#pragma unroll
        for (int pass = 0; pass < 4; pass++) {
            const int shift = 24 - 8 * pass;
            const uint32_t pmask = (pass == 0) ? 0u : (0xFFFFFFFFu << (shift + 8));
            if (tid < 256) hist[tid] = 0;
            __syncthreads();
            const uint32_t prefix = sPrefix;
            const int kth = sKth;
            for (int i = tid; i < cnt; i += NT) {
                uint32_t u = candV[i];
                if ((u & pmask) == prefix) atomicAdd(&hist[(u >> shift) & 0xFFu], 1);
            }
            __syncthreads();
            if (tid < 32) {                   // warp-0 suffix scan of 256 bins
                const int lane = tid;
                const int b0 = lane * 8;
                int s[9];
                s[8] = 0;
                int run = 0;
#pragma unroll
                for (int i = 7; i >= 0; i--) { run += (int)hist[b0 + i]; s[i] = run; }
                int incl = run;
#pragma unroll
                for (int off = 1; off < 32; off <<= 1) {
                    int v = __shfl_down_sync(0xFFFFFFFFu, incl, off);
                    if (lane + off < 32) incl += v;
                }
                int excl = __shfl_down_sync(0xFFFFFFFFu, incl, 1);
                if (lane == 31) excl = 0;
#pragma unroll
                for (int i = 0; i < 8; i++) {
                    int suf = s[i] + excl;        // # candidates >= this bin
                    int nxt = s[i + 1] + excl;    // # candidates strictly above
                    if (suf >= kth && nxt < kth) {   // exactly one (lane,i) hits
                        sPrefix = prefix | ((uint32_t)(b0 + i) << shift);
                        sKth = kth - nxt;            // ties at T to accept
                        sEqTot = suf - nxt;          // ties at T that exist (exact on last pass)
                    }
                }
            }
            __syncthreads();
        }
        T = sPrefix;
        Tf = s2f(T);                          // exact K-th largest value
        eqAllow = sKth;
        eqTotal = sEqTot;
    }

    // ---- Phase 3: re-read row (L2 hits); every address written exactly once. ----
    if (degenerate) {
        // <= K candidates: all elements > cutf win; rest 0 (ReLU handles the rest).
        const float c = cutf;
#pragma unroll 4
        for (int j = 0; j < VEC; j++) {
            const int i = j * NT + tid;
            float4 f = __ldcs(rowv + i);
            float4 o;
            o.x = (f.x > c) ? f.x : 0.0f;
            o.y = (f.y > c) ? f.y : 0.0f;
            o.z = (f.z > c) ? f.z : 0.0f;
            o.w = (f.w > c) ? f.w : 0.0f;
            __stcs(outv + i, o);
        }
    } else if (eqAllow == eqTotal) {
        // All ties at T accepted (no-tie case included): winners are exactly f >= Tf.
        // No atomics -> deterministic and fast.
#pragma unroll 4
        for (int j = 0; j < VEC; j++) {
            const int i = j * NT + tid;
            float4 f = __ldcs(rowv + i);
            float4 o;
            o.x = (f.x >= Tf) ? f.x : 0.0f;
            o.y = (f.y >= Tf) ? f.y : 0.0f;
            o.z = (f.z >= Tf) ? f.z : 0.0f;
            o.w = (f.w >= Tf) ? f.w : 0.0f;
            __stcs(outv + i, o);
        }
    } else {
        // True tie at the rank-K boundary (rare): JAX top_k is stable -> accept the
        // eqAllow SMALLEST column indices among elements == T. Binary search the
        // index cutoff over the candidate list (deterministic, order-independent).
        int lo = 0, hi = COLS - 1;
        while (lo < hi) {
            int mid = (lo + hi) >> 1;
            __syncthreads();
            if (tid == 0) sNum = 0;
            __syncthreads();
            for (int i = tid; i < cnt; i += NT)
                if (candV[i] == T && candI[i] <= mid) atomicAdd(&sNum, 1);
            __syncthreads();
            if (sNum >= eqAllow) hi = mid; else lo = mid + 1;   // uniform: sNum is a pure count
        }
        const int idxCut = lo;                // eqAllow-th smallest tie index
#pragma unroll 4
        for (int j = 0; j < VEC; j++) {
            const int i = j * NT + tid;
            float4 f = __ldcs(rowv + i);
            float4 o;
            o.x = (f.x > Tf || (f.x == Tf && 4*i+0 <= idxCut)) ? f.x : 0.0f;
            o.y = (f.y > Tf || (f.y == Tf && 4*i+1 <= idxCut)) ? f.y : 0.0f;
            o.z = (f.z > Tf || (f.z == Tf && 4*i+2 <= idxCut)) ? f.z : 0.0f;
            o.w = (f.w > Tf || (f.w == Tf && 4*i+3 <= idxCut)) ? f.w : 0.0f;
            __stcs(outv + i, o);
        }
    }
}

extern "C" void kernel_launch(void* const* d_in, const int* in_sizes, int n_in,
                              void* d_out, int out_size) {
    const float* x = (const float*)d_in[0];
    float* out = (float*)d_out;
    int rows = in_sizes[0] / COLS;

    cudaFuncSetAttribute(topk_relu_scatter,
                         cudaFuncAttributeMaxDynamicSharedMemorySize, SMEM_BYTES);
    topk_relu_scatter<<<rows, NT, SMEM_BYTES>>>(x, out);
}

// round 10
// speedup vs baseline: 1.0656x; 1.0656x over previous
#include <cuda_runtime.h>
#include <cstdint>

#define COLS   24576
#define KSEL   64
#define NT     512
#define VEC    (COLS / 4 / NT)     // 12 float4 per thread
#define CAP    3840                // candidate capacity (expected ~152 at cut=2.5)
#define SMEM_BYTES ((CAP * 2 + 256) * 4)   // candV + candI + hist = 31.75 KB -> 4 CTAs/SM

// Monotonic float -> uint32 mapping (order-preserving), candidates only.
__device__ __forceinline__ uint32_t f2s(float f) {
    uint32_t b = __float_as_uint(f);
    return (b & 0x80000000u) ? ~b : (b | 0x80000000u);
}
__device__ __forceinline__ float s2f(uint32_t u) {
    uint32_t b = (u & 0x80000000u) ? (u ^ 0x80000000u) : ~u;
    return __uint_as_float(b);
}

__global__ __launch_bounds__(NT, 4)
void topk_relu_scatter(const float* __restrict__ x, float* __restrict__ out) {
    extern __shared__ uint32_t smem[];
    uint32_t* candV = smem;                   // CAP sortable candidate bits
    int*      candI = (int*)(smem + CAP);     // CAP candidate column indices
    uint32_t* hist  = smem + 2 * CAP;         // 256-bin radix histogram
    __shared__ int sCnt, sKth, sEqTot, sNum;
    __shared__ uint32_t sPrefix;

    const int tid = threadIdx.x;
    const long long row = blockIdx.x;

    if (tid == 0) { sCnt = 0; sKth = KSEL; sEqTot = 1; sPrefix = 0u; }
    __syncthreads();

    const float4* __restrict__ rowv = (const float4*)(x + row * (long long)COLS);
    float4* __restrict__ outv = (float4*)(out + row * (long long)COLS);

    // ---- Phase 1: stream row with DEFAULT caching (L1-allocating, so the
    //      phase-3 re-read can hit L1); vector max filter with a cut high
    //      enough (2.5) that ~46% of warp-visits skip the push branch. ----
    float cutf = 2.5f;
#pragma unroll 4
    for (int j = 0; j < VEC; j++) {
        const int i = j * NT + tid;
        float4 f = rowv[i];
        float m = fmaxf(fmaxf(f.x, f.y), fmaxf(f.z, f.w));
        if (m > cutf) {                       // ~2.4% of vectors
            if (f.x > cutf) { int p = atomicAdd(&sCnt, 1); if (p < CAP) { candV[p] = f2s(f.x); candI[p] = 4*i+0; } }
            if (f.y > cutf) { int p = atomicAdd(&sCnt, 1); if (p < CAP) { candV[p] = f2s(f.y); candI[p] = 4*i+1; } }
            if (f.z > cutf) { int p = atomicAdd(&sCnt, 1); if (p < CAP) { candV[p] = f2s(f.z); candI[p] = 4*i+2; } }
            if (f.w > cutf) { int p = atomicAdd(&sCnt, 1); if (p < CAP) { candV[p] = f2s(f.w); candI[p] = 4*i+3; } }
        }
    }
    __syncthreads();
    int cnt = sCnt;

    // ---- Robustness fallback (never taken for N(0,1); re-read = cache hits) ----
    if (cnt > CAP || cnt < KSEL) {
        cutf = (cnt < KSEL) ? 0.0f : 3.5f;    // ReLU makes cut=0.0 fully general
        __syncthreads();
        if (tid == 0) sCnt = 0;
        __syncthreads();
        for (int j = 0; j < VEC; j++) {
            const int i = j * NT + tid;
            float4 f = rowv[i];
            float m = fmaxf(fmaxf(f.x, f.y), fmaxf(f.z, f.w));
            if (m > cutf) {
                if (f.x > cutf) { int p = atomicAdd(&sCnt, 1); if (p < CAP) { candV[p] = f2s(f.x); candI[p] = 4*i+0; } }
                if (f.y > cutf) { int p = atomicAdd(&sCnt, 1); if (p < CAP) { candV[p] = f2s(f.y); candI[p] = 4*i+1; } }
                if (f.z > cutf) { int p = atomicAdd(&sCnt, 1); if (p < CAP) { candV[p] = f2s(f.z); candI[p] = 4*i+2; } }
                if (f.w > cutf) { int p = atomicAdd(&sCnt, 1); if (p < CAP) { candV[p] = f2s(f.w); candI[p] = 4*i+3; } }
            }
        }
        __syncthreads();
        cnt = min(sCnt, CAP);
    }

    // ---- Phase 2: exact K-th largest among candidates (4x8-bit radix select,
    //      verbatim from the passing R9 kernel) ----
    float Tf = 0.0f;
    uint32_t T = 0u;
    int eqAllow = 0, eqTotal = 0;
    bool degenerate = (cnt <= KSEL);          // all candidates win
    if (!degenerate) {
#pragma unroll
        for (int pass = 0; pass < 4; pass++) {
            const int shift = 24 - 8 * pass;
            const uint32_t pmask = (pass == 0) ? 0u : (0xFFFFFFFFu << (shift + 8));
            if (tid < 256) hist[tid] = 0;
            __syncthreads();
            const uint32_t prefix = sPrefix;
            const int kth = sKth;
            for (int i = tid; i < cnt; i += NT) {
                uint32_t u = candV[i];
                if ((u & pmask) == prefix) atomicAdd(&hist[(u >> shift) & 0xFFu], 1);
            }
            __syncthreads();
            if (tid < 32) {                   // warp-0 suffix scan of 256 bins
                const int lane = tid;
                const int b0 = lane * 8;
                int s[9];
                s[8] = 0;
                int run = 0;
#pragma unroll
                for (int i = 7; i >= 0; i--) { run += (int)hist[b0 + i]; s[i] = run; }
                int incl = run;
#pragma unroll
                for (int off = 1; off < 32; off <<= 1) {
                    int v = __shfl_down_sync(0xFFFFFFFFu, incl, off);
                    if (lane + off < 32) incl += v;
                }
                int excl = __shfl_down_sync(0xFFFFFFFFu, incl, 1);
                if (lane == 31) excl = 0;
#pragma unroll
                for (int i = 0; i < 8; i++) {
                    int suf = s[i] + excl;        // # candidates >= this bin
                    int nxt = s[i + 1] + excl;    // # candidates strictly above
                    if (suf >= kth && nxt < kth) {   // exactly one (lane,i) hits
                        sPrefix = prefix | ((uint32_t)(b0 + i) << shift);
                        sKth = kth - nxt;            // ties at T to accept
                        sEqTot = suf - nxt;          // ties at T that exist (exact on last pass)
                    }
                }
            }
            __syncthreads();
        }
        T = sPrefix;
        Tf = s2f(T);                          // exact K-th largest value
        eqAllow = sKth;
        eqTotal = sEqTot;
    }

    // ---- Phase 3: re-read row (L1/L2 hits); every address written exactly once. ----
    if (degenerate) {
        // <= K candidates: all elements > cutf win; rest 0 (ReLU handles the rest).
        const float c = cutf;
#pragma unroll 4
        for (int j = 0; j < VEC; j++) {
            const int i = j * NT + tid;
            float4 f = __ldcs(rowv + i);
            float4 o;
            o.x = (f.x > c) ? f.x : 0.0f;
            o.y = (f.y > c) ? f.y : 0.0f;
            o.z = (f.z > c) ? f.z : 0.0f;
            o.w = (f.w > c) ? f.w : 0.0f;
            __stcs(outv + i, o);
        }
    } else if (eqAllow == eqTotal) {
        // All ties at T accepted (no-tie case included): winners are exactly f >= Tf.
        // No atomics -> deterministic and fast.
#pragma unroll 4
        for (int j = 0; j < VEC; j++) {
            const int i = j * NT + tid;
            float4 f = __ldcs(rowv + i);
            float4 o;
            o.x = (f.x >= Tf) ? f.x : 0.0f;
            o.y = (f.y >= Tf) ? f.y : 0.0f;
            o.z = (f.z >= Tf) ? f.z : 0.0f;
            o.w = (f.w >= Tf) ? f.w : 0.0f;
            __stcs(outv + i, o);
        }
    } else {
        // True tie at the rank-K boundary (rare): JAX top_k is stable -> accept the
        // eqAllow SMALLEST column indices among elements == T. Binary search the
        // index cutoff over the candidate list (deterministic, order-independent).
        int lo = 0, hi = COLS - 1;
        while (lo < hi) {
            int mid = (lo + hi) >> 1;
            __syncthreads();
            if (tid == 0) sNum = 0;
            __syncthreads();
            for (int i = tid; i < cnt; i += NT)
                if (candV[i] == T && candI[i] <= mid) atomicAdd(&sNum, 1);
            __syncthreads();
            if (sNum >= eqAllow) hi = mid; else lo = mid + 1;   // uniform: sNum is a pure count
        }
        const int idxCut = lo;                // eqAllow-th smallest tie index
#pragma unroll 4
        for (int j = 0; j < VEC; j++) {
            const int i = j * NT + tid;
            float4 f = __ldcs(rowv + i);
            float4 o;
            o.x = (f.x > Tf || (f.x == Tf && 4*i+0 <= idxCut)) ? f.x : 0.0f;
            o.y = (f.y > Tf || (f.y == Tf && 4*i+1 <= idxCut)) ? f.y : 0.0f;
            o.z = (f.z > Tf || (f.z == Tf && 4*i+2 <= idxCut)) ? f.z : 0.0f;
            o.w = (f.w > Tf || (f.w == Tf && 4*i+3 <= idxCut)) ? f.w : 0.0f;
            __stcs(outv + i, o);
        }
    }
}

extern "C" void kernel_launch(void* const* d_in, const int* in_sizes, int n_in,
                              void* d_out, int out_size) {
    const float* x = (const float*)d_in[0];
    float* out = (float*)d_out;
    int rows = in_sizes[0] / COLS;

    cudaFuncSetAttribute(topk_relu_scatter,
                         cudaFuncAttributeMaxDynamicSharedMemorySize, SMEM_BYTES);
    topk_relu_scatter<<<rows, NT, SMEM_BYTES>>>(x, out);
}

// round 15
// speedup vs baseline: 1.0689x; 1.0031x over previous
#include <cuda_runtime.h>
#include <cstdint>

#define COLS   24576
#define KSEL   64
#define NT     512
#define VEC    (COLS / 4 / NT)     // 12 float4 per thread
#define CAP    3072                // candidate capacity (expected ~153 at cut=2.5)
#define SMEM_BYTES ((CAP * 2 + 256) * 4)   // candV + candI + hist = 25.6 KB -> 4 CTAs/SM

// Refilter candidates from gmem at a given cut (robustness path only; never
// taken for N(0,1) rows). Uniform control flow across the block.
__device__ __forceinline__ int refilter(const float4* __restrict__ rowv,
                                        float cutf, uint32_t* candV, int* candI,
                                        int* sCnt, int tid) {
    __syncthreads();
    if (tid == 0) *sCnt = 0;
    __syncthreads();
    for (int j = 0; j < VEC; j++) {
        const int i = j * NT + tid;
        float4 f = rowv[i];
        float m = fmaxf(fmaxf(f.x, f.y), fmaxf(f.z, f.w));
        if (m > cutf) {
            if (f.x > cutf) { int p = atomicAdd(sCnt, 1); if (p < CAP) { candV[p] = __float_as_uint(f.x); candI[p] = 4*i+0; } }
            if (f.y > cutf) { int p = atomicAdd(sCnt, 1); if (p < CAP) { candV[p] = __float_as_uint(f.y); candI[p] = 4*i+1; } }
            if (f.z > cutf) { int p = atomicAdd(sCnt, 1); if (p < CAP) { candV[p] = __float_as_uint(f.z); candI[p] = 4*i+2; } }
            if (f.w > cutf) { int p = atomicAdd(sCnt, 1); if (p < CAP) { candV[p] = __float_as_uint(f.w); candI[p] = 4*i+3; } }
        }
    }
    __syncthreads();
    return *sCnt;
}

__global__ __launch_bounds__(NT, 4)
void topk_relu_scatter(const float* __restrict__ x, float* __restrict__ out) {
    extern __shared__ uint32_t smem[];
    uint32_t* candV = smem;                   // CAP raw float bits (all positive)
    int*      candI = (int*)(smem + CAP);     // CAP column indices
    uint32_t* hist  = smem + 2 * CAP;         // 256-bin radix histogram
    __shared__ int sCnt, sKth, sEqTot, sNum;
    __shared__ uint32_t sPrefix;

    const int tid = threadIdx.x;
    const long long row = blockIdx.x;

    if (tid == 0) { sCnt = 0; sKth = KSEL; sEqTot = 1; sPrefix = 0u; }
    __syncthreads();

    const float4* __restrict__ rowv = (const float4*)(x + row * (long long)COLS);
    float4* __restrict__ outv = (float4*)(out + row * (long long)COLS);
    float* __restrict__ outrow = out + row * (long long)COLS;
    const float4 z4 = make_float4(0.f, 0.f, 0.f, 0.f);

    // ---- Phase 1 (the only heavy pass): stream-read row, stream-write zeros
    //      (independent streams -> both issue immediately, full MLP), push
    //      rare (value, index) candidates. Positive floats: raw-bit order
    //      equals value order, so no sortable conversion needed. ----
    float cutf = 2.5f;
#pragma unroll 4
    for (int j = 0; j < VEC; j++) {
        const int i = j * NT + tid;
        float4 f = __ldcs(rowv + i);
        __stcs(outv + i, z4);                 // zero-fill; winners overwrite in phase 3
        float m = fmaxf(fmaxf(f.x, f.y), fmaxf(f.z, f.w));
        if (m > cutf) {                       // ~2.4% of vectors
            if (f.x > cutf) { int p = atomicAdd(&sCnt, 1); if (p < CAP) { candV[p] = __float_as_uint(f.x); candI[p] = 4*i+0; } }
            if (f.y > cutf) { int p = atomicAdd(&sCnt, 1); if (p < CAP) { candV[p] = __float_as_uint(f.y); candI[p] = 4*i+1; } }
            if (f.z > cutf) { int p = atomicAdd(&sCnt, 1); if (p < CAP) { candV[p] = __float_as_uint(f.z); candI[p] = 4*i+2; } }
            if (f.w > cutf) { int p = atomicAdd(&sCnt, 1); if (p < CAP) { candV[p] = __float_as_uint(f.w); candI[p] = 4*i+3; } }
        }
    }
    __syncthreads();
    int cnt = sCnt;

    // ---- Robustness fallbacks (block-uniform; never taken for N(0,1)) ----
    if (cnt > CAP) {                          // far too many large values
        cnt = refilter(rowv, cutf = 3.5f, candV, candI, &sCnt, tid);
        cnt = min(cnt, CAP);
    } else if (cnt < KSEL) {                  // too few above 2.5
        cnt = refilter(rowv, cutf = 1.25f, candV, candI, &sCnt, tid);
        if (cnt < KSEL) {                     // pathological row: take all positives
            cnt = refilter(rowv, cutf = 0.0f, candV, candI, &sCnt, tid);
            cnt = min(cnt, CAP);              // ReLU makes cut=0.0 fully general
        }
        cnt = min(cnt, CAP);
    }

    // ---- Phase 2: exact K-th largest among candidates (4x8-bit radix select,
    //      verbatim from the passing R9/R10 kernels; raw bits, all positive) ----
    uint32_t T = 0u;
    int eqAllow = 0, eqTotal = 0;
    const bool degenerate = (cnt <= KSEL);    // all candidates win
    if (!degenerate) {
#pragma unroll
        for (int pass = 0; pass < 4; pass++) {
            const int shift = 24 - 8 * pass;
            const uint32_t pmask = (pass == 0) ? 0u : (0xFFFFFFFFu << (shift + 8));
            if (tid < 256) hist[tid] = 0;
            __syncthreads();
            const uint32_t prefix = sPrefix;
            const int kth = sKth;
            for (int i = tid; i < cnt; i += NT) {
                uint32_t u = candV[i];
                if ((u & pmask) == prefix) atomicAdd(&hist[(u >> shift) & 0xFFu], 1);
            }
            __syncthreads();
            if (tid < 32) {                   // warp-0 suffix scan of 256 bins
                const int lane = tid;
                const int b0 = lane * 8;
                int s[9];
                s[8] = 0;
                int run = 0;
#pragma unroll
                for (int i = 7; i >= 0; i--) { run += (int)hist[b0 + i]; s[i] = run; }
                int incl = run;
#pragma unroll
                for (int off = 1; off < 32; off <<= 1) {
                    int v = __shfl_down_sync(0xFFFFFFFFu, incl, off);
                    if (lane + off < 32) incl += v;
                }
                int excl = __shfl_down_sync(0xFFFFFFFFu, incl, 1);
                if (lane == 31) excl = 0;
#pragma unroll
                for (int i = 0; i < 8; i++) {
                    int suf = s[i] + excl;        // # candidates >= this bin
                    int nxt = s[i + 1] + excl;    // # candidates strictly above
                    if (suf >= kth && nxt < kth) {   // exactly one (lane,i) hits
                        sPrefix = prefix | ((uint32_t)(b0 + i) << shift);
                        sKth = kth - nxt;            // ties at T to accept
                        sEqTot = suf - nxt;          // ties at T that exist
                    }
                }
            }
            __syncthreads();
        }
        T = sPrefix;                          // raw bits of the K-th largest
        eqAllow = sKth;
        eqTotal = sEqTot;
    }

    // ---- Phase 3: scatter winners over the barrier-ordered zero fill.
    //      ~64 4-byte stores per row; fully deterministic. ----
    if (degenerate) {
        // <= K candidates: every candidate wins (all > cutf >= 0, ReLU no-op).
        for (int i = tid; i < cnt; i += NT)
            outrow[candI[i]] = __uint_as_float(candV[i]);
    } else if (eqAllow == eqTotal) {
        // All ties at T accepted (includes the no-tie common case).
        for (int i = tid; i < cnt; i += NT) {
            uint32_t u = candV[i];
            if (u >= T) outrow[candI[i]] = __uint_as_float(u);
        }
    } else {
        // True tie at the rank-K boundary (rare): JAX top_k is stable -> accept
        // the eqAllow SMALLEST column indices among elements == T. Deterministic
        // binary search of the index cutoff over the candidate list.
        int lo = 0, hi = COLS - 1;
        while (lo < hi) {
            int mid = (lo + hi) >> 1;
            __syncthreads();
            if (tid == 0) sNum = 0;
            __syncthreads();
            for (int i = tid; i < cnt; i += NT)
                if (candV[i] == T && candI[i] <= mid) atomicAdd(&sNum, 1);
            __syncthreads();
            if (sNum >= eqAllow) hi = mid; else lo = mid + 1;   // sNum is a pure count
        }
        const int idxCut = lo;                // eqAllow-th smallest tie index
        for (int i = tid; i < cnt; i += NT) {
            uint32_t u = candV[i];
            if (u > T || (u == T && candI[i] <= idxCut))
                outrow[candI[i]] = __uint_as_float(u);
        }
    }
}

extern "C" void kernel_launch(void* const* d_in, const int* in_sizes, int n_in,
                              void* d_out, int out_size) {
    const float* x = (const float*)d_in[0];
    float* out = (float*)d_out;
    int rows = in_sizes[0] / COLS;

    cudaFuncSetAttribute(topk_relu_scatter,
                         cudaFuncAttributeMaxDynamicSharedMemorySize, SMEM_BYTES);
    topk_relu_scatter<<<rows, NT, SMEM_BYTES>>>(x, out);
}